// round 3
// baseline (speedup 1.0000x reference)
#include <cuda_runtime.h>

#define BATCH 8
#define NPTS  4096
#define KNN   16
#define GRIDW 96
#define CELLS (BATCH * GRIDW * GRIDW)
#define MAXP  32
#define HID   128
#define OUTC  64
#define WPB   8   // warps per MLP block
#define PP    8   // points per warp (4 pairs)

typedef unsigned long long ull;

// Scratch (static device allocations are allowed)
__device__ int    g_cnt[CELLS];
__device__ float4 g_cell[CELLS * MAXP];              // (x, y, idx_as_float, unused)
__device__ float  g_emb[BATCH * NPTS * 2 * KNN];

// ---------- f32x2 helpers (sm_100+ packed fp32 SIMD) ----------
__device__ __forceinline__ void fma2(ull &d, ull a, ull b) {
    asm("fma.rn.f32x2 %0, %1, %2, %0;" : "+l"(d) : "l"(a), "l"(b));
}
__device__ __forceinline__ ull dup2(float x) {
    ull r; unsigned u = __float_as_uint(x);
    asm("mov.b64 %0, {%1, %1};" : "=l"(r) : "r"(u));
    return r;
}
__device__ __forceinline__ ull pack2(float a, float b) {
    ull r; unsigned ua = __float_as_uint(a), ub = __float_as_uint(b);
    asm("mov.b64 %0, {%1, %2};" : "=l"(r) : "r"(ua), "r"(ub));
    return r;
}
__device__ __forceinline__ float2 unp2(ull v) {
    unsigned a, b;
    asm("mov.b64 {%0, %1}, %2;" : "=r"(a), "=r"(b) : "l"(v));
    return make_float2(__uint_as_float(a), __uint_as_float(b));
}

__global__ void k_zero() {
    int i = blockIdx.x * blockDim.x + threadIdx.x;
    if (i < CELLS) g_cnt[i] = 0;
}

__global__ void k_build(const float4* __restrict__ xytp4) {
    int i = blockIdx.x * blockDim.x + threadIdx.x;
    if (i >= BATCH * NPTS) return;
    float4 v = xytp4[i];
    float x = v.y, y = v.z;
    int cx = min(GRIDW - 1, max(0, (int)(x * (float)GRIDW)));
    int cy = min(GRIDW - 1, max(0, (int)(y * (float)GRIDW)));
    int b = i >> 12;
    int cell = b * GRIDW * GRIDW + cy * GRIDW + cx;
    int p = atomicAdd(&g_cnt[cell], 1);
    if (p < MAXP) g_cell[cell * MAXP + p] = make_float4(x, y, __int_as_float(i & (NPTS - 1)), 0.f);
}

// Ball query: 3x3 cells, keep smallest-16 indices with d2 < R2 (exact replica
// of the reference's float arithmetic), write the 32-float delta embedding.
__global__ void k_query(const float4* __restrict__ xytp4) {
    int i = blockIdx.x * blockDim.x + threadIdx.x;
    if (i >= BATCH * NPTS) return;
    int b = i >> 12;
    int n = i & (NPTS - 1);
    const float4* base4 = xytp4 + (size_t)b * NPTS;
    float4 q = base4[n];
    float xq = q.y, yq = q.z;
    float sqn = __fadd_rn(__fmul_rn(xq, xq), __fmul_rn(yq, yq));
    const float R2 = (float)((5.0 / 480.0) * (5.0 / 480.0));

    int cx = min(GRIDW - 1, max(0, (int)(xq * (float)GRIDW)));
    int cy = min(GRIDW - 1, max(0, (int)(yq * (float)GRIDW)));
    int y0 = max(cy - 1, 0), y1 = min(cy + 1, GRIDW - 1);
    int x0 = max(cx - 1, 0), x1 = min(cx + 1, GRIDW - 1);

    int best[KNN];
    int cnt = 0;

    for (int gy = y0; gy <= y1; gy++) {
        for (int gx = x0; gx <= x1; gx++) {
            int cell = b * GRIDW * GRIDW + gy * GRIDW + gx;
            int c = min(g_cnt[cell], MAXP);
            const float4* cp = g_cell + cell * MAXP;
            for (int j = 0; j < c; j++) {
                float4 pc = cp[j];
                float xm = pc.x, ym = pc.y;
                int   m  = __float_as_int(pc.z);
                float sqm = __fadd_rn(__fmul_rn(xm, xm), __fmul_rn(ym, ym));
                float dot = __fmaf_rn(yq, ym, __fmul_rn(xq, xm));
                float d2  = __fsub_rn(__fadd_rn(sqn, sqm), __fmul_rn(2.0f, dot));
                if (d2 < R2) {
                    if (cnt < KNN) {
                        int t = cnt++;
                        while (t > 0 && best[t - 1] > m) { best[t] = best[t - 1]; t--; }
                        best[t] = m;
                    } else if (m < best[KNN - 1]) {
                        int t = KNN - 1;
                        while (t > 0 && best[t - 1] > m) { best[t] = best[t - 1]; t--; }
                        best[t] = m;
                    }
                }
            }
        }
    }

    float* e = g_emb + (size_t)i * (2 * KNN);
    #pragma unroll
    for (int k = 0; k < KNN; k++) {
        if (k < cnt) {
            float4 t = base4[best[k]];
            e[2 * k]     = __fsub_rn(xq, t.y);
            e[2 * k + 1] = __fsub_rn(yq, t.z);
        } else {
            e[2 * k]     = 0.0f;
            e[2 * k + 1] = 0.0f;
        }
    }
}

// MLP with f32x2 point-pair packing. Warp handles 8 points = 4 pairs.
// Layer 1: lane owns hidden cols 4l..4l+3; acc f32x2 = (pointA, pointB).
// Hidden stored pair-interleaved so layer 2 reads (hA,hB) packs directly.
// Layer 2: lane owns output cols 2l, 2l+1.
extern __shared__ float smem[];
__global__ void __launch_bounds__(WPB * 32) k_mlp(
        const float* __restrict__ W1, const float* __restrict__ b1,
        const float* __restrict__ W2, const float* __restrict__ b2,
        float* __restrict__ out) {
    float* sW1 = smem;                       // 4096
    float* sW2 = sW1 + 32 * HID;             // 8192
    float* sb1 = sW2 + HID * OUTC;           // 128
    float* sb2 = sb1 + HID;                  // 64
    float* sE  = sb2 + OUTC;                 // WPB * 4pairs * 32e * 2 = 2048
    float* sH  = sE + WPB * 256;             // WPB * 4pairs * 128h * 2 = 8192

    int tid  = threadIdx.x;
    int warp = tid >> 5;
    int lane = tid & 31;
    int pbase = blockIdx.x * (WPB * PP);     // block covers 64 points

    for (int j = tid; j < 32 * HID;   j += blockDim.x) sW1[j] = W1[j];
    for (int j = tid; j < HID * OUTC; j += blockDim.x) sW2[j] = W2[j];
    if (tid < HID)  sb1[tid] = b1[tid];
    if (tid < OUTC) sb2[tid] = b2[tid];
    // Stage embeddings pair-interleaved: sE[w*256 + (pr*32+e)*2 + ab]
    for (int j = tid; j < WPB * PP * 32; j += blockDim.x) {
        int lp = j >> 5;              // local point 0..63
        int e  = j & 31;
        int w  = lp >> 3;
        int pr = (lp & 7) >> 1;
        int ab = lp & 1;
        sE[w * 256 + (pr * 32 + e) * 2 + ab] = g_emb[(size_t)(pbase + lp) * 32 + e];
    }
    __syncthreads();

    const float* eb = sE + warp * 256;
    float* hb = sH + warp * 1024;

    // ---- Layer 1 ----
    ull acc[4][4];
    {
        ull b0 = dup2(sb1[4 * lane + 0]);
        ull b1v = dup2(sb1[4 * lane + 1]);
        ull b2v = dup2(sb1[4 * lane + 2]);
        ull b3v = dup2(sb1[4 * lane + 3]);
        #pragma unroll
        for (int pr = 0; pr < 4; pr++) {
            acc[pr][0] = b0; acc[pr][1] = b1v; acc[pr][2] = b2v; acc[pr][3] = b3v;
        }
    }
    #pragma unroll
    for (int e = 0; e < 32; e++) {
        float4 w = *(const float4*)&sW1[e * HID + 4 * lane];
        ull w0 = dup2(w.x), w1 = dup2(w.y), w2 = dup2(w.z), w3 = dup2(w.w);
        #pragma unroll
        for (int pr = 0; pr < 4; pr++) {
            ull v = *(const ull*)&eb[(pr * 32 + e) * 2];   // (embA, embB) broadcast
            fma2(acc[pr][0], v, w0);
            fma2(acc[pr][1], v, w1);
            fma2(acc[pr][2], v, w2);
            fma2(acc[pr][3], v, w3);
        }
    }
    // relu + store pair-interleaved hidden: hb[pr*256 + 2*col]
    #pragma unroll
    for (int pr = 0; pr < 4; pr++) {
        #pragma unroll
        for (int c = 0; c < 4; c++) {
            float2 f = unp2(acc[pr][c]);
            f.x = fmaxf(f.x, 0.0f);
            f.y = fmaxf(f.y, 0.0f);
            acc[pr][c] = pack2(f.x, f.y);
        }
        *(ulonglong2*)&hb[pr * 256 + 8 * lane]     = make_ulonglong2(acc[pr][0], acc[pr][1]);
        *(ulonglong2*)&hb[pr * 256 + 8 * lane + 4] = make_ulonglong2(acc[pr][2], acc[pr][3]);
    }
    __syncwarp();

    // ---- Layer 2 ----
    ull ox[4], oy[4];
    {
        ull bx = dup2(sb2[2 * lane + 0]);
        ull by = dup2(sb2[2 * lane + 1]);
        #pragma unroll
        for (int pr = 0; pr < 4; pr++) { ox[pr] = bx; oy[pr] = by; }
    }
    #pragma unroll 8
    for (int h2 = 0; h2 < HID / 2; h2++) {
        float2 wa = *(const float2*)&sW2[(2 * h2 + 0) * OUTC + 2 * lane];
        float2 wb = *(const float2*)&sW2[(2 * h2 + 1) * OUTC + 2 * lane];
        ull wax = dup2(wa.x), way = dup2(wa.y);
        ull wbx = dup2(wb.x), wby = dup2(wb.y);
        #pragma unroll
        for (int pr = 0; pr < 4; pr++) {
            ulonglong2 hv = *(const ulonglong2*)&hb[pr * 256 + 4 * h2]; // (h0 pair, h1 pair)
            fma2(ox[pr], hv.x, wax);
            fma2(oy[pr], hv.x, way);
            fma2(ox[pr], hv.y, wbx);
            fma2(oy[pr], hv.y, wby);
        }
    }
    // write out: pair pr -> points pbase + warp*8 + 2pr (+1)
    #pragma unroll
    for (int pr = 0; pr < 4; pr++) {
        int pA = pbase + warp * PP + 2 * pr;
        float2 fx = unp2(ox[pr]);
        float2 fy = unp2(oy[pr]);
        *(float2*)&out[(size_t)pA * OUTC + 2 * lane]       = make_float2(fx.x, fy.x);
        *(float2*)&out[(size_t)(pA + 1) * OUTC + 2 * lane] = make_float2(fx.y, fy.y);
    }
}

extern "C" void kernel_launch(void* const* d_in, const int* in_sizes, int n_in,
                              void* d_out, int out_size) {
    const float4* xytp4 = (const float4*)d_in[0];
    const float* W1 = (const float*)d_in[1];
    const float* b1 = (const float*)d_in[2];
    const float* W2 = (const float*)d_in[3];
    const float* b2 = (const float*)d_in[4];
    float* out = (float*)d_out;

    k_zero<<<(CELLS + 255) / 256, 256>>>();
    k_build<<<(BATCH * NPTS + 255) / 256, 256>>>(xytp4);
    k_query<<<(BATCH * NPTS + 127) / 128, 128>>>(xytp4);

    const int smem_floats = 32 * HID + HID * OUTC + HID + OUTC + WPB * 256 + WPB * 1024;
    const int smem_bytes = smem_floats * (int)sizeof(float);
    cudaFuncSetAttribute(k_mlp, cudaFuncAttributeMaxDynamicSharedMemorySize, smem_bytes);
    int nblocks = (BATCH * NPTS) / (WPB * PP);   // 512
    k_mlp<<<nblocks, WPB * 32, smem_bytes>>>(W1, b1, W2, b2, out);
}

// round 4
// speedup vs baseline: 1.2058x; 1.2058x over previous
#include <cuda_runtime.h>

#define BATCH 8
#define NPTS  4096
#define KNN   16
#define GRIDW 96
#define CELLS (BATCH * GRIDW * GRIDW)
#define MAXP  32
#define HID   128
#define OUTC  64
#define WPB   8   // warps per MLP block
#define PP    8   // points per warp (4 pairs)

typedef unsigned long long ull;

// Scratch (static device allocations are allowed)
__device__ int    g_cnt[CELLS];
__device__ float4 g_cell[CELLS * MAXP];   // (x, y, idx_as_float, unused)
__device__ float  g_emb[BATCH * NPTS * 2 * KNN];   // pair-interleaved: [pair][e][ab]
__device__ ull    g_W1d[32 * HID];        // W1 duplicated into both f32x2 halves
__device__ ull    g_W2d[HID * OUTC];      // W2 duplicated

// ---------- f32x2 helpers ----------
__device__ __forceinline__ void fma2(ull &d, ull a, ull b) {
    asm("fma.rn.f32x2 %0, %1, %2, %0;" : "+l"(d) : "l"(a), "l"(b));
}
__device__ __forceinline__ ull dup2(float x) {
    ull r; unsigned u = __float_as_uint(x);
    asm("mov.b64 %0, {%1, %1};" : "=l"(r) : "r"(u));
    return r;
}
__device__ __forceinline__ ull pack2(float a, float b) {
    ull r; unsigned ua = __float_as_uint(a), ub = __float_as_uint(b);
    asm("mov.b64 %0, {%1, %2};" : "=l"(r) : "r"(ua), "r"(ub));
    return r;
}
__device__ __forceinline__ float2 unp2(ull v) {
    unsigned a, b;
    asm("mov.b64 {%0, %1}, %2;" : "=r"(a), "=r"(b) : "l"(v));
    return make_float2(__uint_as_float(a), __uint_as_float(b));
}

__global__ void k_zero() {
    int i = blockIdx.x * blockDim.x + threadIdx.x;
    if (i < CELLS) g_cnt[i] = 0;
}

__global__ void k_dup(const float* __restrict__ W1, const float* __restrict__ W2) {
    int i = blockIdx.x * blockDim.x + threadIdx.x;
    if (i < 32 * HID) g_W1d[i] = dup2(W1[i]);
    int j = i - 32 * HID;
    if (j >= 0 && j < HID * OUTC) g_W2d[j] = dup2(W2[j]);
}

__global__ void k_build(const float4* __restrict__ xytp4) {
    int i = blockIdx.x * blockDim.x + threadIdx.x;
    if (i >= BATCH * NPTS) return;
    float4 v = xytp4[i];
    float x = v.y, y = v.z;
    int cx = min(GRIDW - 1, max(0, (int)(x * (float)GRIDW)));
    int cy = min(GRIDW - 1, max(0, (int)(y * (float)GRIDW)));
    int b = i >> 12;
    int cell = b * GRIDW * GRIDW + cy * GRIDW + cx;
    int p = atomicAdd(&g_cnt[cell], 1);
    if (p < MAXP) g_cell[cell * MAXP + p] = make_float4(x, y, __int_as_float(i & (NPTS - 1)), 0.f);
}

// Ball query: exact replica of the reference's float arithmetic; writes the
// 32-float delta embedding PAIR-INTERLEAVED: g_emb[(i>>1)*64 + 2*j + (i&1)].
__global__ void k_query(const float4* __restrict__ xytp4) {
    int i = blockIdx.x * blockDim.x + threadIdx.x;
    if (i >= BATCH * NPTS) return;
    int b = i >> 12;
    int n = i & (NPTS - 1);
    const float4* base4 = xytp4 + (size_t)b * NPTS;
    float4 q = base4[n];
    float xq = q.y, yq = q.z;
    float sqn = __fadd_rn(__fmul_rn(xq, xq), __fmul_rn(yq, yq));
    const float R2 = (float)((5.0 / 480.0) * (5.0 / 480.0));

    int cx = min(GRIDW - 1, max(0, (int)(xq * (float)GRIDW)));
    int cy = min(GRIDW - 1, max(0, (int)(yq * (float)GRIDW)));
    int y0 = max(cy - 1, 0), y1 = min(cy + 1, GRIDW - 1);
    int x0 = max(cx - 1, 0), x1 = min(cx + 1, GRIDW - 1);

    int best[KNN];
    int cnt = 0;

    for (int gy = y0; gy <= y1; gy++) {
        for (int gx = x0; gx <= x1; gx++) {
            int cell = b * GRIDW * GRIDW + gy * GRIDW + gx;
            int c = min(g_cnt[cell], MAXP);
            const float4* cp = g_cell + cell * MAXP;
            for (int j = 0; j < c; j++) {
                float4 pc = cp[j];
                float xm = pc.x, ym = pc.y;
                int   m  = __float_as_int(pc.z);
                float sqm = __fadd_rn(__fmul_rn(xm, xm), __fmul_rn(ym, ym));
                float dot = __fmaf_rn(yq, ym, __fmul_rn(xq, xm));
                float d2  = __fsub_rn(__fadd_rn(sqn, sqm), __fmul_rn(2.0f, dot));
                if (d2 < R2) {
                    if (cnt < KNN) {
                        int t = cnt++;
                        while (t > 0 && best[t - 1] > m) { best[t] = best[t - 1]; t--; }
                        best[t] = m;
                    } else if (m < best[KNN - 1]) {
                        int t = KNN - 1;
                        while (t > 0 && best[t - 1] > m) { best[t] = best[t - 1]; t--; }
                        best[t] = m;
                    }
                }
            }
        }
    }

    float* e = g_emb + (size_t)(i >> 1) * 64 + (i & 1);
    #pragma unroll
    for (int k = 0; k < KNN; k++) {
        if (k < cnt) {
            float4 t = base4[best[k]];
            e[4 * k]     = __fsub_rn(xq, t.y);
            e[4 * k + 2] = __fsub_rn(yq, t.z);
        } else {
            e[4 * k]     = 0.0f;
            e[4 * k + 2] = 0.0f;
        }
    }
}

// MLP, f32x2 point-pair packed. Warp handles 8 points = 4 pairs.
// Weights come pre-duplicated from GMEM (L1-cached broadcast); smem holds only
// the block's embeddings (8KB) and the hidden activations (32KB).
extern __shared__ float smem[];
__global__ void __launch_bounds__(WPB * 32) k_mlp(
        const float* __restrict__ b1, const float* __restrict__ b2,
        float* __restrict__ out) {
    float* sE = smem;                 // 64 pts * 32 = 2048 floats (pair-interleaved)
    float* sH = sE + 2048;            // 32 pairs * 128 * 2 = 8192 floats

    int tid  = threadIdx.x;
    int warp = tid >> 5;
    int lane = tid & 31;
    int pbase = blockIdx.x * (WPB * PP);     // block covers 64 points = 32 pairs

    // Stage embeddings: contiguous 8KB copy (layout already pair-interleaved)
    {
        const float4* src = (const float4*)(g_emb + (size_t)(pbase >> 1) * 64);
        float4* dst = (float4*)sE;
        #pragma unroll
        for (int j = tid; j < 512; j += WPB * 32) dst[j] = src[j];
    }
    __syncthreads();

    const float* eb = sE + warp * 256;       // this warp's 4 pairs
    float* hb = sH + warp * 1024;

    // ---- Layer 1: lane owns hidden cols 4l..4l+3 ----
    ull acc[4][4];
    {
        float2 ba = __ldg((const float2*)&b1[4 * lane]);
        float2 bbv = __ldg((const float2*)&b1[4 * lane + 2]);
        ull b0 = dup2(ba.x), b1v = dup2(ba.y), b2v = dup2(bbv.x), b3v = dup2(bbv.y);
        #pragma unroll
        for (int pr = 0; pr < 4; pr++) {
            acc[pr][0] = b0; acc[pr][1] = b1v; acc[pr][2] = b2v; acc[pr][3] = b3v;
        }
    }
    #pragma unroll
    for (int e = 0; e < 32; e++) {
        ulonglong2 w01 = __ldg((const ulonglong2*)&g_W1d[e * HID + 4 * lane]);
        ulonglong2 w23 = __ldg((const ulonglong2*)&g_W1d[e * HID + 4 * lane + 2]);
        #pragma unroll
        for (int pr = 0; pr < 4; pr++) {
            ull v = *(const ull*)&eb[pr * 64 + 2 * e];   // (embA, embB) broadcast
            fma2(acc[pr][0], v, w01.x);
            fma2(acc[pr][1], v, w01.y);
            fma2(acc[pr][2], v, w23.x);
            fma2(acc[pr][3], v, w23.y);
        }
    }
    #pragma unroll
    for (int pr = 0; pr < 4; pr++) {
        #pragma unroll
        for (int c = 0; c < 4; c++) {
            float2 f = unp2(acc[pr][c]);
            f.x = fmaxf(f.x, 0.0f);
            f.y = fmaxf(f.y, 0.0f);
            acc[pr][c] = pack2(f.x, f.y);
        }
        *(ulonglong2*)&hb[pr * 256 + 8 * lane]     = make_ulonglong2(acc[pr][0], acc[pr][1]);
        *(ulonglong2*)&hb[pr * 256 + 8 * lane + 4] = make_ulonglong2(acc[pr][2], acc[pr][3]);
    }
    __syncwarp();

    // ---- Layer 2: lane owns output cols 2l, 2l+1 ----
    ull ox[4], oy[4];
    {
        float2 bv = __ldg((const float2*)&b2[2 * lane]);
        ull bx = dup2(bv.x), by = dup2(bv.y);
        #pragma unroll
        for (int pr = 0; pr < 4; pr++) { ox[pr] = bx; oy[pr] = by; }
    }
    #pragma unroll 8
    for (int h2 = 0; h2 < HID / 2; h2++) {
        ulonglong2 wa = __ldg((const ulonglong2*)&g_W2d[(2 * h2 + 0) * OUTC + 2 * lane]);
        ulonglong2 wb = __ldg((const ulonglong2*)&g_W2d[(2 * h2 + 1) * OUTC + 2 * lane]);
        #pragma unroll
        for (int pr = 0; pr < 4; pr++) {
            ulonglong2 hv = *(const ulonglong2*)&hb[pr * 256 + 4 * h2]; // broadcast
            fma2(ox[pr], hv.x, wa.x);
            fma2(oy[pr], hv.x, wa.y);
            fma2(ox[pr], hv.y, wb.x);
            fma2(oy[pr], hv.y, wb.y);
        }
    }
    #pragma unroll
    for (int pr = 0; pr < 4; pr++) {
        int pA = pbase + warp * PP + 2 * pr;
        float2 fx = unp2(ox[pr]);
        float2 fy = unp2(oy[pr]);
        *(float2*)&out[(size_t)pA * OUTC + 2 * lane]       = make_float2(fx.x, fy.x);
        *(float2*)&out[(size_t)(pA + 1) * OUTC + 2 * lane] = make_float2(fx.y, fy.y);
    }
}

extern "C" void kernel_launch(void* const* d_in, const int* in_sizes, int n_in,
                              void* d_out, int out_size) {
    const float4* xytp4 = (const float4*)d_in[0];
    const float* W1 = (const float*)d_in[1];
    const float* b1 = (const float*)d_in[2];
    const float* W2 = (const float*)d_in[3];
    const float* b2 = (const float*)d_in[4];
    float* out = (float*)d_out;

    k_zero<<<(CELLS + 255) / 256, 256>>>();
    k_dup<<<(32 * HID + HID * OUTC + 255) / 256, 256>>>(W1, W2);
    k_build<<<(BATCH * NPTS + 255) / 256, 256>>>(xytp4);
    k_query<<<(BATCH * NPTS + 127) / 128, 128>>>(xytp4);

    const int smem_bytes = (2048 + 8192) * (int)sizeof(float);   // 40 KB
    cudaFuncSetAttribute(k_mlp, cudaFuncAttributeMaxDynamicSharedMemorySize, smem_bytes);
    int nblocks = (BATCH * NPTS) / (WPB * PP);   // 512
    k_mlp<<<nblocks, WPB * 32, smem_bytes>>>(b1, b2, out);
}